// round 2
// baseline (speedup 1.0000x reference)
#include <cuda_runtime.h>
#include <cuda_bf16.h>
#include <cstdint>

// CrossSetNorm: x[B=2048, S=328, D=256] f32, mask[B,S] int32 (nonzero = dead).
// Segment 0 = rows [0,128) with weights_obj/biases_obj,
// Segment 1 = rows [128,328) with weights_road/biases_road.
// Per (batch, segment, feature): masked mean/var over sequence axis, with
// reference quirks:
//   count = clip(sum(alive), min=1); ok = count > 1
//   mean  = ok ? sum1/count : sum1            (raw sum when count<=1)
//   var   = sum_over_ALL_rows (v - mean)^2 / count, where v = x*alive
//         = (sum2 - 2*mean*sum1 + S_seg*mean^2)/count
//   std   = ok ? sqrt(var + 1e-6) : 1
//   out   = (v - mean)/std * w + b            (dead rows: v = 0)

#define B_TOT   2048
#define S_TOT   328
#define D_FEAT  256
#define S_OBJ   128
#define S_ROAD  200
#define NTHREADS 512

// Shared memory layout (floats):
//   [0, 51200)          data tile (max 200*256)
//   [51200, 53248)      sum1 partials [8][256]
//   [53248, 55296)      sum2 partials [8][256]
//   [55296, 55552)      a[256]  (inv_std * w)
//   [55552, 55808)      c[256]  (b - mean * a)
//   [55808, 56008)      alive[200]
//   [56008]             count
#define OFF_DATA   0
#define OFF_RED1   51200
#define OFF_RED2   53248
#define OFF_A      55296
#define OFF_C      55552
#define OFF_ALIVE  55808
#define OFF_CNT    56008
#define SMEM_FLOATS 56012
#define SMEM_BYTES (SMEM_FLOATS * 4)

__global__ void __launch_bounds__(NTHREADS, 1)
cross_set_norm_kernel(const float* __restrict__ x,
                      const int* __restrict__ mask,
                      const float* __restrict__ w_obj,
                      const float* __restrict__ b_obj,
                      const float* __restrict__ w_road,
                      const float* __restrict__ b_road,
                      float* __restrict__ out)
{
    extern __shared__ float smem[];

    const int bid = blockIdx.x;
    const int b   = bid >> 1;
    const int seg = bid & 1;
    const int S   = seg ? S_ROAD : S_OBJ;
    const int off = seg ? S_OBJ : 0;
    const float* __restrict__ wseg = seg ? w_road : w_obj;
    const float* __restrict__ bseg = seg ? b_road : b_obj;

    const size_t row_base = ((size_t)b * S_TOT + off);
    const float* xin  = x    + row_base * D_FEAT;
    float*       outp = out  + row_base * D_FEAT;
    const int*   m    = mask + row_base;

    const int tid = threadIdx.x;
    const int tx  = tid & 63;   // float4 column: features [4*tx, 4*tx+4)
    const int ty  = tid >> 6;   // 0..7 row group

    // ---- Phase A: alive flags into smem -------------------------------
    if (tid < S) {
        smem[OFF_ALIVE + tid] = (m[tid] != 0) ? 0.0f : 1.0f;
    }
    __syncthreads();

    // ---- Phase B: single global read; stage v = x*alive into smem,
    //      accumulate per-thread sum1/sum2 for 4 fixed features ---------
    float s1x = 0.f, s1y = 0.f, s1z = 0.f, s1w = 0.f;
    float s2x = 0.f, s2y = 0.f, s2z = 0.f, s2w = 0.f;

    const float4* __restrict__ xv = reinterpret_cast<const float4*>(xin);
    float4* datav = reinterpret_cast<float4*>(smem + OFF_DATA);

    #pragma unroll 4
    for (int s = ty; s < S; s += 8) {
        float al = smem[OFF_ALIVE + s];
        float4 v = xv[s * 64 + tx];
        v.x *= al; v.y *= al; v.z *= al; v.w *= al;
        datav[s * 64 + tx] = v;
        s1x += v.x; s1y += v.y; s1z += v.z; s1w += v.w;
        s2x += v.x * v.x; s2y += v.y * v.y; s2z += v.z * v.z; s2w += v.w * v.w;
    }

    {
        float4* r1 = reinterpret_cast<float4*>(smem + OFF_RED1);
        float4* r2 = reinterpret_cast<float4*>(smem + OFF_RED2);
        r1[ty * 64 + tx] = make_float4(s1x, s1y, s1z, s1w);
        r2[ty * 64 + tx] = make_float4(s2x, s2y, s2z, s2w);
    }
    __syncthreads();

    // ---- Phase C: per-feature reduce + count + coefficients -----------
    float S1 = 0.f, S2 = 0.f;
    if (tid < 256) {
        #pragma unroll
        for (int k = 0; k < 8; k++) {
            S1 += smem[OFF_RED1 + k * 256 + tid];
            S2 += smem[OFF_RED2 + k * 256 + tid];
        }
    } else if (tid < 288) {
        // warp 8 computes the alive count
        int lane = tid & 31;
        float c = 0.f;
        for (int s = lane; s < S; s += 32) c += smem[OFF_ALIVE + s];
        #pragma unroll
        for (int o = 16; o > 0; o >>= 1) c += __shfl_down_sync(0xffffffffu, c, o);
        if (lane == 0) smem[OFF_CNT] = c;
    }
    __syncthreads();

    if (tid < 256) {
        float cnt = smem[OFF_CNT];
        float cc  = fmaxf(cnt, 1.0f);
        bool  ok  = cnt > 1.0f;
        float mean = ok ? (S1 / cc) : S1;
        float var  = (S2 - 2.0f * mean * S1 + (float)S * mean * mean) / cc;
        float inv  = ok ? rsqrtf(var + 1e-6f) : 1.0f;
        float a = inv * wseg[tid];
        float c = bseg[tid] - mean * a;
        smem[OFF_A + tid] = a;
        smem[OFF_C + tid] = c;
    }
    __syncthreads();

    // ---- Phase D: fused epilogue, single global write -----------------
    const int d0 = tx * 4;
    float a0 = smem[OFF_A + d0 + 0], a1 = smem[OFF_A + d0 + 1];
    float a2 = smem[OFF_A + d0 + 2], a3 = smem[OFF_A + d0 + 3];
    float c0 = smem[OFF_C + d0 + 0], c1 = smem[OFF_C + d0 + 1];
    float c2 = smem[OFF_C + d0 + 2], c3 = smem[OFF_C + d0 + 3];

    float4* outv = reinterpret_cast<float4*>(outp);
    #pragma unroll 4
    for (int s = ty; s < S; s += 8) {
        float4 v = datav[s * 64 + tx];
        float4 o;
        o.x = fmaf(v.x, a0, c0);
        o.y = fmaf(v.y, a1, c1);
        o.z = fmaf(v.z, a2, c2);
        o.w = fmaf(v.w, a3, c3);
        outv[s * 64 + tx] = o;
    }
}

extern "C" void kernel_launch(void* const* d_in, const int* in_sizes, int n_in,
                              void* d_out, int out_size)
{
    const float* x      = (const float*)d_in[0];
    const int*   mask   = (const int*)d_in[1];
    const float* w_obj  = (const float*)d_in[2];
    const float* b_obj  = (const float*)d_in[3];
    const float* w_road = (const float*)d_in[4];
    const float* b_road = (const float*)d_in[5];
    float* out = (float*)d_out;

    cudaFuncSetAttribute(cross_set_norm_kernel,
                         cudaFuncAttributeMaxDynamicSharedMemorySize, SMEM_BYTES);

    dim3 grid(B_TOT * 2);
    dim3 block(NTHREADS);
    cross_set_norm_kernel<<<grid, block, SMEM_BYTES>>>(
        x, mask, w_obj, b_obj, w_road, b_road, out);
}

// round 4
// speedup vs baseline: 1.1394x; 1.1394x over previous
#include <cuda_runtime.h>
#include <cuda_bf16.h>
#include <cstdint>

// CrossSetNorm: x[B=2048, S=328, D=256] f32, mask[B,S] int32 (nonzero = dead).
// Each CTA: one (batch, segment, feature-half). 2 CTAs/SM (100KB tiles).

#define B_TOT   2048
#define S_TOT   328
#define D_FEAT  256
#define D_HALF  128
#define S_OBJ   128
#define S_ROAD  200
#define NTHREADS 512

// Shared memory layout (floats), per CTA:
//   [0, 25600)            data tile (max 200*128)
//   [25600, 26624)        sum1 partials [8][128]
//   [26624, 27648)        sum2 partials [8][128]
//   [27648, 27776)        a[128]  (inv_std * w)
//   [27776, 27904)        c[128]  (b - mean * a)
//   [27904, 28104)        alive[200]
//   [28104]               count
#define OFF_DATA   0
#define OFF_RED1   25600
#define OFF_RED2   26624
#define OFF_A      27648
#define OFF_C      27776
#define OFF_ALIVE  27904
#define OFF_CNT    28104
#define SMEM_FLOATS 28108
#define SMEM_BYTES (SMEM_FLOATS * 4)

__global__ void __launch_bounds__(NTHREADS, 2)
cross_set_norm_kernel(const float* __restrict__ x,
                      const int* __restrict__ mask,
                      const float* __restrict__ w_obj,
                      const float* __restrict__ b_obj,
                      const float* __restrict__ w_road,
                      const float* __restrict__ b_road,
                      float* __restrict__ out)
{
    extern __shared__ float smem[];

    const int bid  = blockIdx.x;
    const int half = bid & 1;          // feature half: 0 -> [0,128), 1 -> [128,256)
    const int seg  = (bid >> 1) & 1;   // 0 = obj, 1 = road
    const int b    = bid >> 2;

    const int S   = seg ? S_ROAD : S_OBJ;
    const int off = seg ? S_OBJ : 0;
    const int fo  = half * D_HALF;
    const float* __restrict__ wseg = (seg ? w_road : w_obj) + fo;
    const float* __restrict__ bseg = (seg ? b_road : b_obj) + fo;

    const size_t row_base = ((size_t)b * S_TOT + off);
    const float* xin  = x    + row_base * D_FEAT + fo;
    float*       outp = out  + row_base * D_FEAT + fo;
    const int*   m    = mask + row_base;

    const int tid = threadIdx.x;
    const int tx  = tid & 31;   // float4 column: features [4*tx, 4*tx+4) within half
    const int ty  = tid >> 5;   // 0..15 row group (= warp id)

    // ---- Phase A: alive flags ----------------------------------------
    if (tid < S) {
        smem[OFF_ALIVE + tid] = (m[tid] != 0) ? 0.0f : 1.0f;
    }
    __syncthreads();

    // ---- Phase B: single global read; stage v = x*alive into smem,
    //      accumulate per-thread sum1/sum2 for 4 fixed features ---------
    float s1x = 0.f, s1y = 0.f, s1z = 0.f, s1w = 0.f;
    float s2x = 0.f, s2y = 0.f, s2z = 0.f, s2w = 0.f;

    float4* datav = reinterpret_cast<float4*>(smem + OFF_DATA);

    #pragma unroll 4
    for (int s = ty; s < S; s += 16) {
        float al = smem[OFF_ALIVE + s];
        const float4* rowp = reinterpret_cast<const float4*>(xin + (size_t)s * D_FEAT);
        float4 v = rowp[tx];
        v.x *= al; v.y *= al; v.z *= al; v.w *= al;
        datav[s * 32 + tx] = v;
        s1x += v.x; s1y += v.y; s1z += v.z; s1w += v.w;
        s2x += v.x * v.x; s2y += v.y * v.y; s2z += v.z * v.z; s2w += v.w * v.w;
    }

    // ---- Phase C1: fold 16 row-group partials -> 8 in smem ------------
    float4* r1 = reinterpret_cast<float4*>(smem + OFF_RED1);
    float4* r2 = reinterpret_cast<float4*>(smem + OFF_RED2);
    if (ty >= 8) {
        r1[(ty - 8) * 32 + tx] = make_float4(s1x, s1y, s1z, s1w);
        r2[(ty - 8) * 32 + tx] = make_float4(s2x, s2y, s2z, s2w);
    }
    __syncthreads();
    if (ty < 8) {
        float4 p1 = r1[ty * 32 + tx];
        float4 p2 = r2[ty * 32 + tx];
        p1.x += s1x; p1.y += s1y; p1.z += s1z; p1.w += s1w;
        p2.x += s2x; p2.y += s2y; p2.z += s2z; p2.w += s2w;
        r1[ty * 32 + tx] = p1;
        r2[ty * 32 + tx] = p2;
    }
    __syncthreads();

    // ---- Phase C2: per-feature reduce (128 threads) + count (warp 4..) -
    float S1 = 0.f, S2 = 0.f;
    if (tid < D_HALF) {
        #pragma unroll
        for (int k = 0; k < 8; k++) {
            S1 += smem[OFF_RED1 + k * D_HALF + tid];
            S2 += smem[OFF_RED2 + k * D_HALF + tid];
        }
    } else if (tid < D_HALF + 32) {
        int lane = tid & 31;
        float c = 0.f;
        for (int s = lane; s < S; s += 32) c += smem[OFF_ALIVE + s];
        #pragma unroll
        for (int o = 16; o > 0; o >>= 1) c += __shfl_down_sync(0xffffffffu, c, o);
        if (lane == 0) smem[OFF_CNT] = c;
    }
    __syncthreads();

    if (tid < D_HALF) {
        float cnt = smem[OFF_CNT];
        float cc  = fmaxf(cnt, 1.0f);
        bool  ok  = cnt > 1.0f;
        float mean = ok ? (S1 / cc) : S1;
        float var  = (S2 - 2.0f * mean * S1 + (float)S * mean * mean) / cc;
        float inv  = ok ? rsqrtf(var + 1e-6f) : 1.0f;
        float a = inv * wseg[tid];
        float c = bseg[tid] - mean * a;
        smem[OFF_A + tid] = a;
        smem[OFF_C + tid] = c;
    }
    __syncthreads();

    // ---- Phase D: fused epilogue, single global write -----------------
    const int d0 = tx * 4;
    float a0 = smem[OFF_A + d0 + 0], a1 = smem[OFF_A + d0 + 1];
    float a2 = smem[OFF_A + d0 + 2], a3 = smem[OFF_A + d0 + 3];
    float c0 = smem[OFF_C + d0 + 0], c1 = smem[OFF_C + d0 + 1];
    float c2 = smem[OFF_C + d0 + 2], c3 = smem[OFF_C + d0 + 3];

    #pragma unroll 4
    for (int s = ty; s < S; s += 16) {
        float4 v = datav[s * 32 + tx];
        float4 o;
        o.x = fmaf(v.x, a0, c0);
        o.y = fmaf(v.y, a1, c1);
        o.z = fmaf(v.z, a2, c2);
        o.w = fmaf(v.w, a3, c3);
        float4* orow = reinterpret_cast<float4*>(outp + (size_t)s * D_FEAT);
        orow[tx] = o;
    }
}

extern "C" void kernel_launch(void* const* d_in, const int* in_sizes, int n_in,
                              void* d_out, int out_size)
{
    const float* x      = (const float*)d_in[0];
    const int*   mask   = (const int*)d_in[1];
    const float* w_obj  = (const float*)d_in[2];
    const float* b_obj  = (const float*)d_in[3];
    const float* w_road = (const float*)d_in[4];
    const float* b_road = (const float*)d_in[5];
    float* out = (float*)d_out;

    cudaFuncSetAttribute(cross_set_norm_kernel,
                         cudaFuncAttributeMaxDynamicSharedMemorySize, SMEM_BYTES);

    dim3 grid(B_TOT * 4);   // b * (2 segs) * (2 feature halves)
    dim3 block(NTHREADS);
    cross_set_norm_kernel<<<grid, block, SMEM_BYTES>>>(
        x, mask, w_obj, b_obj, w_road, b_road, out);
}

// round 5
// speedup vs baseline: 1.4165x; 1.2432x over previous
#include <cuda_runtime.h>
#include <cuda_bf16.h>
#include <cstdint>

// CrossSetNorm: x[B=2048, S=328, D=256] f32, mask[B,S] int32 (nonzero = dead).
// Each CTA: one (batch, segment, feature-half). 2 CTAs/SM (100KB tiles).
// R5: cp.async staging of RAW x (mask applied algebraically afterwards) to
// decouple the global-read stream from all computation.

#define B_TOT   2048
#define S_TOT   328
#define D_FEAT  256
#define D_HALF  128
#define S_OBJ   128
#define S_ROAD  200
#define NTHREADS 512

// Shared memory layout (floats), per CTA:
//   [0, 25600)            raw x tile (max 200*128)
//   [25600, 26624)        sum1 partials [8][128]
//   [26624, 27648)        sum2 partials [8][128]
//   [27648, 27776)        a[128]  (inv_std * w)
//   [27776, 27904)        c[128]  (b - mean * a)
//   [27904, 28104)        alive[200]
//   [28104]               count
#define OFF_DATA   0
#define OFF_RED1   25600
#define OFF_RED2   26624
#define OFF_A      27648
#define OFF_C      27776
#define OFF_ALIVE  27904
#define OFF_CNT    28104
#define SMEM_FLOATS 28108
#define SMEM_BYTES (SMEM_FLOATS * 4)

__device__ __forceinline__ void cp_async16(uint32_t smem_addr, const void* gptr) {
    asm volatile("cp.async.cg.shared.global [%0], [%1], 16;\n"
                 :: "r"(smem_addr), "l"(gptr) : "memory");
}

__global__ void __launch_bounds__(NTHREADS, 2)
cross_set_norm_kernel(const float* __restrict__ x,
                      const int* __restrict__ mask,
                      const float* __restrict__ w_obj,
                      const float* __restrict__ b_obj,
                      const float* __restrict__ w_road,
                      const float* __restrict__ b_road,
                      float* __restrict__ out)
{
    extern __shared__ float smem[];

    const int bid  = blockIdx.x;
    const int half = bid & 1;          // feature half: 0 -> [0,128), 1 -> [128,256)
    const int seg  = (bid >> 1) & 1;   // 0 = obj, 1 = road
    const int b    = bid >> 2;

    const int S   = seg ? S_ROAD : S_OBJ;
    const int off = seg ? S_OBJ : 0;
    const int fo  = half * D_HALF;
    const float* __restrict__ wseg = (seg ? w_road : w_obj) + fo;
    const float* __restrict__ bseg = (seg ? b_road : b_obj) + fo;

    const size_t row_base = ((size_t)b * S_TOT + off);
    const float* xin  = x    + row_base * D_FEAT + fo;
    float*       outp = out  + row_base * D_FEAT + fo;
    const int*   m    = mask + row_base;

    const int tid = threadIdx.x;
    const int tx  = tid & 31;   // float4 column: features [4*tx, 4*tx+4) within half
    const int ty  = tid >> 5;   // 0..15 row group (= warp id)

    // ---- Phase A: fire the whole tile via cp.async (raw x, not gated on
    //      the mask), plus the alive flags ------------------------------
    {
        uint32_t sbase = (uint32_t)__cvta_generic_to_shared(smem + OFF_DATA);
        #pragma unroll
        for (int s = ty; s < S_ROAD; s += 16) {     // max trip count; guard inside
            if (s < S) {
                cp_async16(sbase + (uint32_t)(s * 32 + tx) * 16,
                           xin + (size_t)s * D_FEAT + tx * 4);
            }
        }
        asm volatile("cp.async.commit_group;\n" ::: "memory");
    }
    if (tid < S) {
        smem[OFF_ALIVE + tid] = (m[tid] != 0) ? 0.0f : 1.0f;
    }
    asm volatile("cp.async.wait_group 0;\n" ::: "memory");
    __syncthreads();

    // ---- Phase B: sum pass from smem (v = x * alive) ------------------
    float s1x = 0.f, s1y = 0.f, s1z = 0.f, s1w = 0.f;
    float s2x = 0.f, s2y = 0.f, s2z = 0.f, s2w = 0.f;

    float4* datav = reinterpret_cast<float4*>(smem + OFF_DATA);

    #pragma unroll 4
    for (int s = ty; s < S; s += 16) {
        float al = smem[OFF_ALIVE + s];
        float4 v = datav[s * 32 + tx];
        v.x *= al; v.y *= al; v.z *= al; v.w *= al;
        s1x += v.x; s1y += v.y; s1z += v.z; s1w += v.w;
        s2x += v.x * v.x; s2y += v.y * v.y; s2z += v.z * v.z; s2w += v.w * v.w;
    }

    // ---- Phase C1: fold 16 row-group partials -> 8 in smem ------------
    float4* r1 = reinterpret_cast<float4*>(smem + OFF_RED1);
    float4* r2 = reinterpret_cast<float4*>(smem + OFF_RED2);
    if (ty >= 8) {
        r1[(ty - 8) * 32 + tx] = make_float4(s1x, s1y, s1z, s1w);
        r2[(ty - 8) * 32 + tx] = make_float4(s2x, s2y, s2z, s2w);
    }
    __syncthreads();
    if (ty < 8) {
        float4 p1 = r1[ty * 32 + tx];
        float4 p2 = r2[ty * 32 + tx];
        p1.x += s1x; p1.y += s1y; p1.z += s1z; p1.w += s1w;
        p2.x += s2x; p2.y += s2y; p2.z += s2z; p2.w += s2w;
        r1[ty * 32 + tx] = p1;
        r2[ty * 32 + tx] = p2;
    }
    __syncthreads();

    // ---- Phase C2: per-feature reduce (128 threads) + count -----------
    float S1 = 0.f, S2 = 0.f;
    if (tid < D_HALF) {
        #pragma unroll
        for (int k = 0; k < 8; k++) {
            S1 += smem[OFF_RED1 + k * D_HALF + tid];
            S2 += smem[OFF_RED2 + k * D_HALF + tid];
        }
    } else if (tid < D_HALF + 32) {
        int lane = tid & 31;
        float c = 0.f;
        for (int s = lane; s < S; s += 32) c += smem[OFF_ALIVE + s];
        #pragma unroll
        for (int o = 16; o > 0; o >>= 1) c += __shfl_down_sync(0xffffffffu, c, o);
        if (lane == 0) smem[OFF_CNT] = c;
    }
    __syncthreads();

    if (tid < D_HALF) {
        float cnt = smem[OFF_CNT];
        float cc  = fmaxf(cnt, 1.0f);
        bool  ok  = cnt > 1.0f;
        float mean = ok ? (S1 / cc) : S1;
        float var  = (S2 - 2.0f * mean * S1 + (float)S * mean * mean) / cc;
        float inv  = ok ? rsqrtf(var + 1e-6f) : 1.0f;
        float a = inv * wseg[tid];
        float c = bseg[tid] - mean * a;
        smem[OFF_A + tid] = a;
        smem[OFF_C + tid] = c;
    }
    __syncthreads();

    // ---- Phase D: fused epilogue; out = x*(al*a) + c ------------------
    const int d0 = tx * 4;
    float a0 = smem[OFF_A + d0 + 0], a1 = smem[OFF_A + d0 + 1];
    float a2 = smem[OFF_A + d0 + 2], a3 = smem[OFF_A + d0 + 3];
    float c0 = smem[OFF_C + d0 + 0], c1 = smem[OFF_C + d0 + 1];
    float c2 = smem[OFF_C + d0 + 2], c3 = smem[OFF_C + d0 + 3];

    #pragma unroll 4
    for (int s = ty; s < S; s += 16) {
        float al = smem[OFF_ALIVE + s];
        float4 v = datav[s * 32 + tx];
        float4 o;
        o.x = fmaf(v.x, al * a0, c0);
        o.y = fmaf(v.y, al * a1, c1);
        o.z = fmaf(v.z, al * a2, c2);
        o.w = fmaf(v.w, al * a3, c3);
        float4* orow = reinterpret_cast<float4*>(outp + (size_t)s * D_FEAT);
        orow[tx] = o;
    }
}

extern "C" void kernel_launch(void* const* d_in, const int* in_sizes, int n_in,
                              void* d_out, int out_size)
{
    const float* x      = (const float*)d_in[0];
    const int*   mask   = (const int*)d_in[1];
    const float* w_obj  = (const float*)d_in[2];
    const float* b_obj  = (const float*)d_in[3];
    const float* w_road = (const float*)d_in[4];
    const float* b_road = (const float*)d_in[5];
    float* out = (float*)d_out;

    cudaFuncSetAttribute(cross_set_norm_kernel,
                         cudaFuncAttributeMaxDynamicSharedMemorySize, SMEM_BYTES);

    dim3 grid(B_TOT * 4);   // b * (2 segs) * (2 feature halves)
    dim3 block(NTHREADS);
    cross_set_norm_kernel<<<grid, block, SMEM_BYTES>>>(
        x, mask, w_obj, b_obj, w_road, b_road, out);
}